// round 15
// baseline (speedup 1.0000x reference)
#include <cuda_runtime.h>
#include <cstdint>

#define N_NODES 100000
#define IN_DIM  512
#define HIDDEN  16
#define OUT_DIM 64

__device__ float g_deg [N_NODES];
__device__ float g_dinv[N_NODES];
__device__ float g_hs1 [N_NODES * HIDDEN];
__device__ float g_acc1[N_NODES * HIDDEN];
__device__ float g_zs  [N_NODES * HIDDEN];
__device__ float g_acc2[N_NODES * HIDDEN];

// ---------------------------------------------------------------------------
__global__ void k_degree(const int* __restrict__ dst, int E) {
    int e0 = (blockIdx.x * blockDim.x + threadIdx.x) << 2;
    if (e0 + 3 < E) {
        int4 d = *reinterpret_cast<const int4*>(dst + e0);
        atomicAdd(&g_deg[d.x], 1.0f);
        atomicAdd(&g_deg[d.y], 1.0f);
        atomicAdd(&g_deg[d.z], 1.0f);
        atomicAdd(&g_deg[d.w], 1.0f);
    } else {
        for (int e = e0; e < E; e++) atomicAdd(&g_deg[dst[e]], 1.0f);
    }
}

// ---------------------------------------------------------------------------
// GEMM1: 3x-tf32 mma.sync + per-warp cp.async.bulk (TMA) pipeline.
// hs1[n][f] = (sum_k x[n][k]*W1[k][f]) * dinv[n]; fuses dinv + acc1 zeroing.
// 8 warps x 16 rows; each warp stages its own rows via 16x128B bulk copies
// per chunk, completion via warp-private mbarrier ring (3 stages).
#define G1_ROWS 128
#define G1_KC   32
#define XS_STR  36                   // floats/row: 128B data + 16B pad
#define N_CHUNK (IN_DIM / G1_KC)     // 16
#define N_STG   3
#define WSTG_FLT (16 * XS_STR)       // 576 floats / warp / stage
#define STG_FLT  (8 * WSTG_FLT)      // 4608 floats / stage
#define MB_OFF   (N_STG * STG_FLT * 4)          // mbarrier region offset
#define SMEM_TOT (MB_OFF + 8 * N_STG * 8)       // + 8 warps * 3 mbars

#define TF32_HI(u) ((u) & 0xFFFFE000u)

__device__ __forceinline__ void mma_tf32(float c[4],
                                         uint32_t a0, uint32_t a1,
                                         uint32_t a2, uint32_t a3,
                                         uint32_t b0, uint32_t b1) {
    asm("mma.sync.aligned.m16n8k8.row.col.f32.tf32.tf32.f32 "
        "{%0,%1,%2,%3}, {%4,%5,%6,%7}, {%8,%9}, {%0,%1,%2,%3};"
        : "+f"(c[0]), "+f"(c[1]), "+f"(c[2]), "+f"(c[3])
        : "r"(a0), "r"(a1), "r"(a2), "r"(a3), "r"(b0), "r"(b1));
}

__device__ __forceinline__ void mbar_init(uint32_t a) {
    asm volatile("mbarrier.init.shared.b64 [%0], 1;" :: "r"(a) : "memory");
}
__device__ __forceinline__ void mbar_expect_tx(uint32_t a, uint32_t bytes) {
    asm volatile("mbarrier.arrive.expect_tx.shared.b64 _, [%0], %1;"
                 :: "r"(a), "r"(bytes) : "memory");
}
__device__ __forceinline__ void mbar_wait(uint32_t a, uint32_t parity) {
    asm volatile(
        "{\n\t.reg .pred P;\n\tWL_%=:\n\t"
        "mbarrier.try_wait.parity.acquire.cta.shared::cta.b64 P, [%0], %1, 0x989680;\n\t"
        "@P bra.uni WD_%=;\n\tbra.uni WL_%=;\n\tWD_%=:\n\t}"
        :: "r"(a), "r"(parity) : "memory");
}
__device__ __forceinline__ void bulk_cp128(uint32_t dst, const void* src,
                                           uint32_t mbar) {
    asm volatile(
        "cp.async.bulk.shared::cluster.global.mbarrier::complete_tx::bytes "
        "[%0], [%1], 128, [%2];"
        :: "r"(dst), "l"(src), "r"(mbar) : "memory");
}

__global__ __launch_bounds__(256) void k_gemm1(const float* __restrict__ x,
                                               const float* __restrict__ W1) {
    extern __shared__ float xs[];
    uint32_t sb;
    asm("{ .reg .u64 t; cvta.to.shared.u64 t, %1; cvt.u32.u64 %0, t; }"
        : "=r"(sb) : "l"(xs));

    int tid  = threadIdx.x;
    int warp = tid >> 5, lane = tid & 31;
    int gid  = lane >> 2, tq = lane & 3;
    int row0 = blockIdx.x * G1_ROWS;

    uint32_t wsm = sb + warp * WSTG_FLT * 4;           // warp slice, stage 0
    uint32_t mb0 = sb + MB_OFF + warp * N_STG * 8;     // warp's 3 mbarriers

    if (lane == 0) {
        mbar_init(mb0);
        mbar_init(mb0 + 8);
        mbar_init(mb0 + 16);
    }
    asm volatile("fence.proxy.async.shared::cta;" ::: "memory");
    __syncwarp();

    // clamped per-row global sources (tail block)
    const float* xrow[16];
    #pragma unroll
    for (int rr = 0; rr < 16; rr++) {
        int grow = row0 + warp * 16 + rr;
        if (grow >= N_NODES) grow = N_NODES - 1;
        xrow[rr] = x + (size_t)grow * IN_DIM;
    }

    float c[2][4] = {{0.f, 0.f, 0.f, 0.f}, {0.f, 0.f, 0.f, 0.f}};

    // prologue: issue chunks 0, 1
    if (lane == 0) {
        #pragma unroll
        for (int p = 0; p < 2; p++) {
            uint32_t mb = mb0 + p * 8;
            mbar_expect_tx(mb, 16 * 128);
            uint32_t soff = (uint32_t)(p * STG_FLT * 4);
            #pragma unroll
            for (int rr = 0; rr < 16; rr++)
                bulk_cp128(wsm + soff + rr * (XS_STR * 4),
                           xrow[rr] + p * G1_KC, mb);
        }
    }

    for (int ch = 0; ch < N_CHUNK; ch++) {
        int st = ch % N_STG;
        mbar_wait(mb0 + st * 8, (uint32_t)((ch / N_STG) & 1));
        __syncwarp();

        if (lane == 0 && ch + 2 < N_CHUNK) {
            int st2 = (ch + 2) % N_STG;
            uint32_t mb = mb0 + st2 * 8;
            mbar_expect_tx(mb, 16 * 128);
            uint32_t soff = (uint32_t)(st2 * STG_FLT * 4);
            #pragma unroll
            for (int rr = 0; rr < 16; rr++)
                bulk_cp128(wsm + soff + rr * (XS_STR * 4),
                           xrow[rr] + (ch + 2) * G1_KC, mb);
        }

        const float* xb = &xs[warp * WSTG_FLT + st * STG_FLT];
        int kc = ch * G1_KC;

        #pragma unroll
        for (int kt = 0; kt < G1_KC / 8; kt++) {
            const float* ap = &xb[gid * XS_STR + kt * 8 + tq];
            float a0f = ap[0];
            float a2f = ap[4];
            float a1f = ap[8 * XS_STR];
            float a3f = ap[8 * XS_STR + 4];
            uint32_t ah0 = TF32_HI(__float_as_uint(a0f));
            uint32_t ah1 = TF32_HI(__float_as_uint(a1f));
            uint32_t ah2 = TF32_HI(__float_as_uint(a2f));
            uint32_t ah3 = TF32_HI(__float_as_uint(a3f));
            uint32_t al0 = __float_as_uint(a0f - __uint_as_float(ah0));
            uint32_t al1 = __float_as_uint(a1f - __uint_as_float(ah1));
            uint32_t al2 = __float_as_uint(a2f - __uint_as_float(ah2));
            uint32_t al3 = __float_as_uint(a3f - __uint_as_float(ah3));

            int krow = kc + kt * 8 + tq;
            #pragma unroll
            for (int nt = 0; nt < 2; nt++) {
                float b0f = __ldg(&W1[krow * HIDDEN + nt * 8 + gid]);
                float b1f = __ldg(&W1[(krow + 4) * HIDDEN + nt * 8 + gid]);
                uint32_t bh0 = TF32_HI(__float_as_uint(b0f));
                uint32_t bh1 = TF32_HI(__float_as_uint(b1f));
                uint32_t bl0 = __float_as_uint(b0f - __uint_as_float(bh0));
                uint32_t bl1 = __float_as_uint(b1f - __uint_as_float(bh1));
                mma_tf32(c[nt], ah0, ah1, ah2, ah3, bh0, bh1);
                mma_tf32(c[nt], al0, al1, al2, al3, bh0, bh1);
                mma_tf32(c[nt], ah0, ah1, ah2, ah3, bl0, bl1);
            }
        }
    }

    // epilogue: fused dinv + acc1 zeroing
    int r0 = row0 + warp * 16 + gid;
    int r1 = r0 + 8;
    float dv0 = 0.f, dv1 = 0.f;
    if (r0 < N_NODES) dv0 = rsqrtf(g_deg[r0] + 1.0f);
    if (r1 < N_NODES) dv1 = rsqrtf(g_deg[r1] + 1.0f);
    if (tq == 0) {
        if (r0 < N_NODES) g_dinv[r0] = dv0;
        if (r1 < N_NODES) g_dinv[r1] = dv1;
    }
    float2 zz = make_float2(0.f, 0.f);
    #pragma unroll
    for (int nt = 0; nt < 2; nt++) {
        int f = nt * 8 + tq * 2;
        if (r0 < N_NODES) {
            float2 v = make_float2(c[nt][0] * dv0, c[nt][1] * dv0);
            *reinterpret_cast<float2*>(&g_hs1[r0 * HIDDEN + f]) = v;
            *reinterpret_cast<float2*>(&g_acc1[r0 * HIDDEN + f]) = zz;
        }
        if (r1 < N_NODES) {
            float2 v = make_float2(c[nt][2] * dv1, c[nt][3] * dv1);
            *reinterpret_cast<float2*>(&g_hs1[r1 * HIDDEN + f]) = v;
            *reinterpret_cast<float2*>(&g_acc1[r1 * HIDDEN + f]) = zz;
        }
    }
}

// ---------------------------------------------------------------------------
// Edge scatter: acc[dst] += table[src] (16 floats). Quad handles 8 edges.
__device__ __forceinline__ void red_add_v4(float* p, float4 v) {
    asm volatile("red.global.add.v4.f32 [%0], {%1,%2,%3,%4};"
                 :: "l"(p), "f"(v.x), "f"(v.y), "f"(v.z), "f"(v.w) : "memory");
}

__global__ __launch_bounds__(256) void k_scatter(const int* __restrict__ src,
                                                 const int* __restrict__ dst,
                                                 int E, int phase) {
    int t = blockIdx.x * blockDim.x + threadIdx.x;
    int e0 = (t >> 2) << 3;
    if (e0 >= E) return;
    int q = (t & 3) << 2;
    const float* tab = phase ? g_zs   : g_hs1;
    float*       acc = phase ? g_acc2 : g_acc1;

    if (e0 + 7 < E) {
        int4 sa = *reinterpret_cast<const int4*>(src + e0);
        int4 sb = *reinterpret_cast<const int4*>(src + e0 + 4);
        int4 da = *reinterpret_cast<const int4*>(dst + e0);
        int4 db = *reinterpret_cast<const int4*>(dst + e0 + 4);
        float4 v0 = *reinterpret_cast<const float4*>(tab + sa.x * HIDDEN + q);
        float4 v1 = *reinterpret_cast<const float4*>(tab + sa.y * HIDDEN + q);
        float4 v2 = *reinterpret_cast<const float4*>(tab + sa.z * HIDDEN + q);
        float4 v3 = *reinterpret_cast<const float4*>(tab + sa.w * HIDDEN + q);
        float4 v4 = *reinterpret_cast<const float4*>(tab + sb.x * HIDDEN + q);
        float4 v5 = *reinterpret_cast<const float4*>(tab + sb.y * HIDDEN + q);
        float4 v6 = *reinterpret_cast<const float4*>(tab + sb.z * HIDDEN + q);
        float4 v7 = *reinterpret_cast<const float4*>(tab + sb.w * HIDDEN + q);
        red_add_v4(acc + da.x * HIDDEN + q, v0);
        red_add_v4(acc + da.y * HIDDEN + q, v1);
        red_add_v4(acc + da.z * HIDDEN + q, v2);
        red_add_v4(acc + da.w * HIDDEN + q, v3);
        red_add_v4(acc + db.x * HIDDEN + q, v4);
        red_add_v4(acc + db.y * HIDDEN + q, v5);
        red_add_v4(acc + db.z * HIDDEN + q, v6);
        red_add_v4(acc + db.w * HIDDEN + q, v7);
    } else {
        for (int e = e0; e < E; e++) {
            int s = src[e], d = dst[e];
            float4 v = *reinterpret_cast<const float4*>(tab + s * HIDDEN + q);
            red_add_v4(acc + d * HIDDEN + q, v);
        }
    }
}

// ---------------------------------------------------------------------------
// Layer-1 epilogue: zs = relu(dinv*(acc1+hs1) + b1) * dinv; zeroes acc2.
__global__ void k_mid(const float* __restrict__ b1) {
    int i = blockIdx.x * blockDim.x + threadIdx.x;
    if (i >= N_NODES * HIDDEN / 4) return;
    int node = i >> 2;
    int f4 = (i & 3) << 2;
    float dv = g_dinv[node];
    float4 a = *reinterpret_cast<const float4*>(&g_acc1[i * 4]);
    float4 h = *reinterpret_cast<const float4*>(&g_hs1[i * 4]);
    float4 b = *reinterpret_cast<const float4*>(&b1[f4]);
    float4 z;
    z.x = fmaxf(fmaf(dv, a.x + h.x, b.x), 0.f) * dv;
    z.y = fmaxf(fmaf(dv, a.y + h.y, b.y), 0.f) * dv;
    z.z = fmaxf(fmaf(dv, a.z + h.z, b.z), 0.f) * dv;
    z.w = fmaxf(fmaf(dv, a.w + h.w, b.w), 0.f) * dv;
    *reinterpret_cast<float4*>(&g_zs[i * 4]) = z;
    *reinterpret_cast<float4*>(&g_acc2[i * 4]) = make_float4(0.f, 0.f, 0.f, 0.f);
}

// ---------------------------------------------------------------------------
// Final GEMM + deg re-zero for next launch (replaces k_zero_deg).
__global__ __launch_bounds__(256) void k_final(const float* __restrict__ W2,
                                               const float* __restrict__ b2,
                                               float* __restrict__ out) {
    __shared__ float W2s[HIDDEN * OUT_DIM];
    __shared__ float aggs[4][HIDDEN];
    int tid = threadIdx.x;
    for (int j = tid; j < HIDDEN * OUT_DIM; j += 256) W2s[j] = W2[j];

    int n = tid >> 6;
    int o = tid & 63;
    int node = blockIdx.x * 4 + n;

    if (o < HIDDEN) {
        float dv = g_dinv[node];
        int idx = node * HIDDEN + o;
        aggs[n][o] = dv * (g_acc2[idx] + g_zs[idx]);
    }
    if (tid < 4) g_deg[blockIdx.x * 4 + tid] = 0.f;   // reset for next launch
    __syncthreads();

    float acc = b2[o];
    #pragma unroll
    for (int k = 0; k < HIDDEN; k++)
        acc = fmaf(aggs[n][k], W2s[k * OUT_DIM + o], acc);
    out[(size_t)node * OUT_DIM + o] = acc;
}

// ---------------------------------------------------------------------------
extern "C" void kernel_launch(void* const* d_in, const int* in_sizes, int n_in,
                              void* d_out, int out_size) {
    const float* x  = (const float*)d_in[0];
    const float* W1 = (const float*)d_in[1];
    const float* b1 = (const float*)d_in[2];
    const float* W2 = (const float*)d_in[3];
    const float* b2 = (const float*)d_in[4];
    const int*   ei = (const int*)d_in[5];
    float* out = (float*)d_out;

    int E = in_sizes[5] / 2;
    const int* src = ei;
    const int* dst = ei + E;

    cudaFuncSetAttribute(k_gemm1, cudaFuncAttributeMaxDynamicSharedMemorySize,
                         SMEM_TOT);

    k_degree <<<(E / 4 + 255) / 256, 256>>>(dst, E);
    k_gemm1  <<<(N_NODES + G1_ROWS - 1) / G1_ROWS, 256, SMEM_TOT>>>(x, W1);
    k_scatter<<<(E / 2 + 255) / 256, 256>>>(src, dst, E, 0);
    k_mid    <<<(N_NODES * HIDDEN / 4 + 255) / 256, 256>>>(b1);
    k_scatter<<<(E / 2 + 255) / 256, 256>>>(src, dst, E, 1);
    k_final  <<<N_NODES / 4, 256>>>(W2, b2, out);
}

// round 16
// speedup vs baseline: 1.2315x; 1.2315x over previous
#include <cuda_runtime.h>
#include <cstdint>

#define N_NODES 100000
#define IN_DIM  512
#define HIDDEN  16
#define OUT_DIM 64

__device__ float g_deg [N_NODES];
__device__ float g_dinv[N_NODES];
__device__ float g_hs1 [N_NODES * HIDDEN];
__device__ float g_acc1[N_NODES * HIDDEN];
__device__ float g_zs  [N_NODES * HIDDEN];
__device__ float g_acc2[N_NODES * HIDDEN];

// ---------------------------------------------------------------------------
__global__ void k_degree(const int* __restrict__ dst, int E) {
    int e0 = (blockIdx.x * blockDim.x + threadIdx.x) << 2;
    if (e0 + 3 < E) {
        int4 d = *reinterpret_cast<const int4*>(dst + e0);
        atomicAdd(&g_deg[d.x], 1.0f);
        atomicAdd(&g_deg[d.y], 1.0f);
        atomicAdd(&g_deg[d.z], 1.0f);
        atomicAdd(&g_deg[d.w], 1.0f);
    } else {
        for (int e = e0; e < E; e++) atomicAdd(&g_deg[dst[e]], 1.0f);
    }
}

// ---------------------------------------------------------------------------
// GEMM1 (R14 winner, dinv-decoupled): h[n][f] = sum_k x[n][k]*W1[k][f]
// 3x-tf32 mma.sync + per-warp autonomous cp.async pipeline; zeroes acc1.
#define G1_ROWS 128
#define G1_KC   32
#define XS_STR  36
#define N_CHUNK (IN_DIM / G1_KC)     // 16
#define N_STG   3
#define WSTG_FLT (16 * XS_STR)       // 576 floats per warp per stage
#define STG_FLT  (8 * WSTG_FLT)      // 4608 floats per stage

#define TF32_HI(u) ((u) & 0xFFFFE000u)

__device__ __forceinline__ void cp_async16(unsigned int saddr, const void* gptr) {
    asm volatile("cp.async.cg.shared.global [%0], [%1], 16;"
                 :: "r"(saddr), "l"(gptr) : "memory");
}

__device__ __forceinline__ void mma_tf32(float c[4],
                                         uint32_t a0, uint32_t a1,
                                         uint32_t a2, uint32_t a3,
                                         uint32_t b0, uint32_t b1) {
    asm("mma.sync.aligned.m16n8k8.row.col.f32.tf32.tf32.f32 "
        "{%0,%1,%2,%3}, {%4,%5,%6,%7}, {%8,%9}, {%0,%1,%2,%3};"
        : "+f"(c[0]), "+f"(c[1]), "+f"(c[2]), "+f"(c[3])
        : "r"(a0), "r"(a1), "r"(a2), "r"(a3), "r"(b0), "r"(b1));
}

__global__ __launch_bounds__(256) void k_gemm1(const float* __restrict__ x,
                                               const float* __restrict__ W1) {
    extern __shared__ float xs[];

    int tid  = threadIdx.x;
    int warp = tid >> 5, lane = tid & 31;
    int gid  = lane >> 2, tq = lane & 3;
    int row0 = blockIdx.x * G1_ROWS;

    const float4* xg = reinterpret_cast<const float4*>(x);
    float* wbase = &xs[warp * WSTG_FLT];

    int s_rr[4], s_cc[4];
    const float4* s_g[4];
    unsigned int s_sm[4];
    #pragma unroll
    for (int l = 0; l < 4; l++) {
        int idx = lane + l * 32;
        s_rr[l] = idx >> 3;
        s_cc[l] = idx & 7;
        int grow = row0 + warp * 16 + s_rr[l];
        if (grow >= N_NODES) grow = N_NODES - 1;
        s_g[l]  = &xg[(size_t)grow * (IN_DIM / 4) + s_cc[l]];
        s_sm[l] = (unsigned int)__cvta_generic_to_shared(
                      &wbase[s_rr[l] * XS_STR + s_cc[l] * 4]);
    }

    float c[2][4] = {{0.f, 0.f, 0.f, 0.f}, {0.f, 0.f, 0.f, 0.f}};

    #pragma unroll
    for (int p = 0; p < 2; p++) {
        unsigned int soff = (unsigned int)((p % N_STG) * STG_FLT * 4);
        #pragma unroll
        for (int l = 0; l < 4; l++)
            cp_async16(s_sm[l] + soff, s_g[l] + p * (G1_KC / 4));
        asm volatile("cp.async.commit_group;");
    }

    for (int ch = 0; ch < N_CHUNK; ch++) {
        asm volatile("cp.async.wait_group 1;");
        __syncwarp();

        if (ch + 2 < N_CHUNK) {
            unsigned int soff = (unsigned int)(((ch + 2) % N_STG) * STG_FLT * 4);
            #pragma unroll
            for (int l = 0; l < 4; l++)
                cp_async16(s_sm[l] + soff, s_g[l] + (ch + 2) * (G1_KC / 4));
        }
        asm volatile("cp.async.commit_group;");

        const float* xb = &wbase[(ch % N_STG) * STG_FLT];
        int kc = ch * G1_KC;

        #pragma unroll
        for (int kt = 0; kt < G1_KC / 8; kt++) {
            const float* ap = &xb[gid * XS_STR + kt * 8 + tq];
            float a0f = ap[0];
            float a2f = ap[4];
            float a1f = ap[8 * XS_STR];
            float a3f = ap[8 * XS_STR + 4];
            uint32_t ah0 = TF32_HI(__float_as_uint(a0f));
            uint32_t ah1 = TF32_HI(__float_as_uint(a1f));
            uint32_t ah2 = TF32_HI(__float_as_uint(a2f));
            uint32_t ah3 = TF32_HI(__float_as_uint(a3f));
            uint32_t al0 = __float_as_uint(a0f - __uint_as_float(ah0));
            uint32_t al1 = __float_as_uint(a1f - __uint_as_float(ah1));
            uint32_t al2 = __float_as_uint(a2f - __uint_as_float(ah2));
            uint32_t al3 = __float_as_uint(a3f - __uint_as_float(ah3));

            int krow = kc + kt * 8 + tq;
            #pragma unroll
            for (int nt = 0; nt < 2; nt++) {
                float b0f = __ldg(&W1[krow * HIDDEN + nt * 8 + gid]);
                float b1f = __ldg(&W1[(krow + 4) * HIDDEN + nt * 8 + gid]);
                uint32_t bh0 = TF32_HI(__float_as_uint(b0f));
                uint32_t bh1 = TF32_HI(__float_as_uint(b1f));
                uint32_t bl0 = __float_as_uint(b0f - __uint_as_float(bh0));
                uint32_t bl1 = __float_as_uint(b1f - __uint_as_float(bh1));
                mma_tf32(c[nt], ah0, ah1, ah2, ah3, bh0, bh1);
                mma_tf32(c[nt], al0, al1, al2, al3, bh0, bh1);
                mma_tf32(c[nt], ah0, ah1, ah2, ah3, bl0, bl1);
            }
        }
    }

    // epilogue: raw h + acc1 zeroing (dinv applied later in k_scale)
    int r0 = row0 + warp * 16 + gid;
    int r1 = r0 + 8;
    float2 zz = make_float2(0.f, 0.f);
    #pragma unroll
    for (int nt = 0; nt < 2; nt++) {
        int f = nt * 8 + tq * 2;
        if (r0 < N_NODES) {
            float2 v = make_float2(c[nt][0], c[nt][1]);
            *reinterpret_cast<float2*>(&g_hs1[r0 * HIDDEN + f]) = v;
            *reinterpret_cast<float2*>(&g_acc1[r0 * HIDDEN + f]) = zz;
        }
        if (r1 < N_NODES) {
            float2 v = make_float2(c[nt][2], c[nt][3]);
            *reinterpret_cast<float2*>(&g_hs1[r1 * HIDDEN + f]) = v;
            *reinterpret_cast<float2*>(&g_acc1[r1 * HIDDEN + f]) = zz;
        }
    }
}

// ---------------------------------------------------------------------------
// k_scale (join point): dinv = rsqrt(deg+1); hs1 *= dinv (in place).
__global__ void k_scale() {
    int i = blockIdx.x * blockDim.x + threadIdx.x;      // float4 index
    if (i >= N_NODES * HIDDEN / 4) return;
    int node = i >> 2;
    float dv = rsqrtf(g_deg[node] + 1.0f);
    if ((i & 3) == 0) g_dinv[node] = dv;
    float4 h = *reinterpret_cast<const float4*>(&g_hs1[i * 4]);
    h.x *= dv; h.y *= dv; h.z *= dv; h.w *= dv;
    *reinterpret_cast<float4*>(&g_hs1[i * 4]) = h;
}

// ---------------------------------------------------------------------------
// Edge scatter: acc[dst] += table[src] (16 floats). Quad handles 8 edges.
__device__ __forceinline__ void red_add_v4(float* p, float4 v) {
    asm volatile("red.global.add.v4.f32 [%0], {%1,%2,%3,%4};"
                 :: "l"(p), "f"(v.x), "f"(v.y), "f"(v.z), "f"(v.w) : "memory");
}

__global__ __launch_bounds__(256) void k_scatter(const int* __restrict__ src,
                                                 const int* __restrict__ dst,
                                                 int E, int phase) {
    int t = blockIdx.x * blockDim.x + threadIdx.x;
    int e0 = (t >> 2) << 3;
    if (e0 >= E) return;
    int q = (t & 3) << 2;
    const float* tab = phase ? g_zs   : g_hs1;
    float*       acc = phase ? g_acc2 : g_acc1;

    if (e0 + 7 < E) {
        int4 sa = *reinterpret_cast<const int4*>(src + e0);
        int4 sb = *reinterpret_cast<const int4*>(src + e0 + 4);
        int4 da = *reinterpret_cast<const int4*>(dst + e0);
        int4 db = *reinterpret_cast<const int4*>(dst + e0 + 4);
        float4 v0 = *reinterpret_cast<const float4*>(tab + sa.x * HIDDEN + q);
        float4 v1 = *reinterpret_cast<const float4*>(tab + sa.y * HIDDEN + q);
        float4 v2 = *reinterpret_cast<const float4*>(tab + sa.z * HIDDEN + q);
        float4 v3 = *reinterpret_cast<const float4*>(tab + sa.w * HIDDEN + q);
        float4 v4 = *reinterpret_cast<const float4*>(tab + sb.x * HIDDEN + q);
        float4 v5 = *reinterpret_cast<const float4*>(tab + sb.y * HIDDEN + q);
        float4 v6 = *reinterpret_cast<const float4*>(tab + sb.z * HIDDEN + q);
        float4 v7 = *reinterpret_cast<const float4*>(tab + sb.w * HIDDEN + q);
        red_add_v4(acc + da.x * HIDDEN + q, v0);
        red_add_v4(acc + da.y * HIDDEN + q, v1);
        red_add_v4(acc + da.z * HIDDEN + q, v2);
        red_add_v4(acc + da.w * HIDDEN + q, v3);
        red_add_v4(acc + db.x * HIDDEN + q, v4);
        red_add_v4(acc + db.y * HIDDEN + q, v5);
        red_add_v4(acc + db.z * HIDDEN + q, v6);
        red_add_v4(acc + db.w * HIDDEN + q, v7);
    } else {
        for (int e = e0; e < E; e++) {
            int s = src[e], d = dst[e];
            float4 v = *reinterpret_cast<const float4*>(tab + s * HIDDEN + q);
            red_add_v4(acc + d * HIDDEN + q, v);
        }
    }
}

// ---------------------------------------------------------------------------
// Layer-1 epilogue: zs = relu(dinv*(acc1+hs1) + b1) * dinv; zeroes acc2.
__global__ void k_mid(const float* __restrict__ b1) {
    int i = blockIdx.x * blockDim.x + threadIdx.x;
    if (i >= N_NODES * HIDDEN / 4) return;
    int node = i >> 2;
    int f4 = (i & 3) << 2;
    float dv = g_dinv[node];
    float4 a = *reinterpret_cast<const float4*>(&g_acc1[i * 4]);
    float4 h = *reinterpret_cast<const float4*>(&g_hs1[i * 4]);
    float4 b = *reinterpret_cast<const float4*>(&b1[f4]);
    float4 z;
    z.x = fmaxf(fmaf(dv, a.x + h.x, b.x), 0.f) * dv;
    z.y = fmaxf(fmaf(dv, a.y + h.y, b.y), 0.f) * dv;
    z.z = fmaxf(fmaf(dv, a.z + h.z, b.z), 0.f) * dv;
    z.w = fmaxf(fmaf(dv, a.w + h.w, b.w), 0.f) * dv;
    *reinterpret_cast<float4*>(&g_zs[i * 4]) = z;
    *reinterpret_cast<float4*>(&g_acc2[i * 4]) = make_float4(0.f, 0.f, 0.f, 0.f);
}

// ---------------------------------------------------------------------------
// Final GEMM + deg re-zero for next launch.
__global__ __launch_bounds__(256) void k_final(const float* __restrict__ W2,
                                               const float* __restrict__ b2,
                                               float* __restrict__ out) {
    __shared__ float W2s[HIDDEN * OUT_DIM];
    __shared__ float aggs[4][HIDDEN];
    int tid = threadIdx.x;
    for (int j = tid; j < HIDDEN * OUT_DIM; j += 256) W2s[j] = W2[j];

    int n = tid >> 6;
    int o = tid & 63;
    int node = blockIdx.x * 4 + n;

    if (o < HIDDEN) {
        float dv = g_dinv[node];
        int idx = node * HIDDEN + o;
        aggs[n][o] = dv * (g_acc2[idx] + g_zs[idx]);
    }
    if (tid < 4) g_deg[blockIdx.x * 4 + tid] = 0.f;   // reset for next launch
    __syncthreads();

    float acc = b2[o];
    #pragma unroll
    for (int k = 0; k < HIDDEN; k++)
        acc = fmaf(aggs[n][k], W2s[k * OUT_DIM + o], acc);
    out[(size_t)node * OUT_DIM + o] = acc;
}

// ---------------------------------------------------------------------------
extern "C" void kernel_launch(void* const* d_in, const int* in_sizes, int n_in,
                              void* d_out, int out_size) {
    const float* x  = (const float*)d_in[0];
    const float* W1 = (const float*)d_in[1];
    const float* b1 = (const float*)d_in[2];
    const float* W2 = (const float*)d_in[3];
    const float* b2 = (const float*)d_in[4];
    const int*   ei = (const int*)d_in[5];
    float* out = (float*)d_out;

    int E = in_sizes[5] / 2;
    const int* src = ei;
    const int* dst = ei + E;

    const int smem_bytes = N_STG * STG_FLT * 4;   // 55296
    cudaFuncSetAttribute(k_gemm1, cudaFuncAttributeMaxDynamicSharedMemorySize,
                         smem_bytes);

    // Fork: k_degree (main stream 0) runs concurrently with k_gemm1 (side).
    cudaStream_t side = 0;
    cudaEvent_t ev_fork = 0, ev_join = 0;
    bool forked =
        (cudaStreamCreateWithFlags(&side, cudaStreamNonBlocking) == cudaSuccess) &&
        (cudaEventCreateWithFlags(&ev_fork, cudaEventDisableTiming) == cudaSuccess) &&
        (cudaEventCreateWithFlags(&ev_join, cudaEventDisableTiming) == cudaSuccess);

    if (forked) {
        cudaEventRecord(ev_fork, 0);
        cudaStreamWaitEvent(side, ev_fork, 0);
        k_gemm1 <<<(N_NODES + G1_ROWS - 1) / G1_ROWS, 256, smem_bytes, side>>>(x, W1);
        k_degree<<<(E / 4 + 255) / 256, 256>>>(dst, E);
        cudaEventRecord(ev_join, side);
        cudaStreamWaitEvent(0, ev_join, 0);
    } else {
        k_degree<<<(E / 4 + 255) / 256, 256>>>(dst, E);
        k_gemm1 <<<(N_NODES + G1_ROWS - 1) / G1_ROWS, 256, smem_bytes>>>(x, W1);
    }

    k_scale  <<<(N_NODES * HIDDEN / 4 + 255) / 256, 256>>>();
    k_scatter<<<(E / 2 + 255) / 256, 256>>>(src, dst, E, 0);
    k_mid    <<<(N_NODES * HIDDEN / 4 + 255) / 256, 256>>>(b1);
    k_scatter<<<(E / 2 + 255) / 256, 256>>>(src, dst, E, 1);
    k_final  <<<N_NODES / 4, 256>>>(W2, b2, out);

    if (forked) {
        cudaStreamDestroy(side);
        cudaEventDestroy(ev_fork);
        cudaEventDestroy(ev_join);
    }
}